// round 1
// baseline (speedup 1.0000x reference)
#include <cuda_runtime.h>
#include <cuda_bf16.h>
#include <math.h>

// Problem constants (fixed by the reference setup_inputs)
#define NB 256   // batches
#define NA 64    // atoms
#define NE 128   // edges per batch
#define NK 6     // neighbors per edge
#define NH 256   // hidden
#define NH4 (NH / 4)   // 64 float4 per edge row

__global__ __launch_bounds__(256)
void directed_edge_message_kernel(const float* __restrict__ rep,     // [1,B,E,H]
                                  const int*   __restrict__ pairs,   // [B,E,2]
                                  const int*   __restrict__ nbrs,    // [B,E,K]
                                  const float* __restrict__ xyz,     // [B,A,3]
                                  float*       __restrict__ out)     // [1,B,E,H]
{
    const int b   = blockIdx.x;
    const int tid = threadIdx.x;

    __shared__ float dist_s[NE];
    __shared__ int   nb_s[NE * NK];

    // ---- Phase 1: per-edge inverse-squared-distance weight -----------------
    if (tid < NE) {
        const int base = (b * NE + tid) * 2;
        const int p0 = pairs[base + 0];
        const int p1 = pairs[base + 1];
        const float* x0 = xyz + ((size_t)b * NA + p0) * 3;
        const float* x1 = xyz + ((size_t)b * NA + p1) * 3;
        const float dx = x0[0] - x1[0];
        const float dy = x0[1] - x1[1];
        const float dz = x0[2] - x1[2];
        const float d2 = dx * dx + dy * dy + dz * dz;
        float inv = 1.0f / d2;
        // match jnp.where(isinf(inv), 0, inv)
        dist_s[tid] = isinf(inv) ? 0.0f : inv;
    }

    // Stage neighbor indices for this batch (E*K = 768 ints)
    #pragma unroll
    for (int i = tid; i < NE * NK; i += 256) {
        nb_s[i] = nbrs[(size_t)b * NE * NK + i];
    }
    __syncthreads();

    // ---- Phase 2: gather + weighted sum ------------------------------------
    const float4* __restrict__ rep4 = reinterpret_cast<const float4*>(rep + (size_t)b * NE * NH);
    float4*       __restrict__ out4 = reinterpret_cast<float4*>(out + (size_t)b * NE * NH);

    // E * NH4 = 8192 float4 outputs per block; 32 per thread.
    #pragma unroll 4
    for (int i = tid; i < NE * NH4; i += 256) {
        const int e = i >> 6;          // / NH4
        const int h = i & (NH4 - 1);   // % NH4

        float4 acc = make_float4(0.f, 0.f, 0.f, 0.f);
        #pragma unroll
        for (int k = 0; k < NK; k++) {
            const int   nb = nb_s[e * NK + k];
            const float w  = dist_s[nb];
            const float4 v = rep4[nb * NH4 + h];
            acc.x = fmaf(w, v.x, acc.x);
            acc.y = fmaf(w, v.y, acc.y);
            acc.z = fmaf(w, v.z, acc.z);
            acc.w = fmaf(w, v.w, acc.w);
        }
        out4[i] = acc;
    }
}

extern "C" void kernel_launch(void* const* d_in, const int* in_sizes, int n_in,
                              void* d_out, int out_size)
{
    const float* rep   = (const float*)d_in[0];  // bond_representations [1,B,E,H]
    const int*   pairs = (const int*)  d_in[1];  // bond_pairs          [B,E,2]
    const int*   nbrs  = (const int*)  d_in[2];  // bond_neighbors      [B,E,K]
    const float* xyz   = (const float*)d_in[3];  // xyz                 [B,A,3]
    float*       out   = (float*)d_out;          // [1,B,E,H]

    directed_edge_message_kernel<<<NB, 256>>>(rep, pairs, nbrs, xyz, out);
}

// round 2
// speedup vs baseline: 1.5212x; 1.5212x over previous
#include <cuda_runtime.h>
#include <cuda_bf16.h>
#include <math.h>

// Problem constants (fixed by the reference setup_inputs)
#define NB 256   // batches
#define NA 64    // atoms
#define NE 128   // edges per batch
#define NK 6     // neighbors per edge
#define NH 256   // hidden
#define NH4 (NH / 4)     // 64 float4 per edge row
#define HSPLIT 4         // CTAs per batch along H
#define NH4S (NH4 / HSPLIT)  // 16 float4 per edge per CTA

__global__ __launch_bounds__(256)
void directed_edge_message_kernel(const float* __restrict__ rep,     // [1,B,E,H]
                                  const int*   __restrict__ pairs,   // [B,E,2]
                                  const int*   __restrict__ nbrs,    // [B,E,K]
                                  const float* __restrict__ xyz,     // [B,A,3]
                                  float*       __restrict__ out)     // [1,B,E,H]
{
    const int b   = blockIdx.x;
    const int hs  = blockIdx.y;            // 0..HSPLIT-1
    const int tid = threadIdx.x;

    __shared__ float dist_s[NE];
    __shared__ int   nb_s[NE * NK];

    // ---- Phase 1: per-edge inverse-squared-distance weight -----------------
    if (tid < NE) {
        const int base = (b * NE + tid) * 2;
        const int p0 = pairs[base + 0];
        const int p1 = pairs[base + 1];
        const float* x0 = xyz + ((size_t)b * NA + p0) * 3;
        const float* x1 = xyz + ((size_t)b * NA + p1) * 3;
        const float dx = x0[0] - x1[0];
        const float dy = x0[1] - x1[1];
        const float dz = x0[2] - x1[2];
        const float d2 = dx * dx + dy * dy + dz * dz;
        float inv = 1.0f / d2;
        // match jnp.where(isinf(inv), 0, inv)
        dist_s[tid] = isinf(inv) ? 0.0f : inv;
    }

    // Stage neighbor indices for this batch (E*K = 768 ints)
    #pragma unroll
    for (int i = tid; i < NE * NK; i += 256) {
        nb_s[i] = nbrs[(size_t)b * NE * NK + i];
    }
    __syncthreads();

    // ---- Phase 2: gather + weighted sum ------------------------------------
    const float4* __restrict__ rep4 = reinterpret_cast<const float4*>(rep + (size_t)b * NE * NH);
    float4*       __restrict__ out4 = reinterpret_cast<float4*>(out + (size_t)b * NE * NH);
    const int hbase = hs * NH4S;

    // This CTA: NE * NH4S = 2048 float4 outputs; 8 per thread.
    #pragma unroll 2
    for (int i = tid; i < NE * NH4S; i += 256) {
        const int e = i >> 4;               // / NH4S
        const int h = hbase + (i & (NH4S - 1));

        float4 acc = make_float4(0.f, 0.f, 0.f, 0.f);
        #pragma unroll
        for (int k = 0; k < NK; k++) {
            const int   nb = nb_s[e * NK + k];
            const float w  = dist_s[nb];
            const float4 v = rep4[nb * NH4 + h];
            acc.x = fmaf(w, v.x, acc.x);
            acc.y = fmaf(w, v.y, acc.y);
            acc.z = fmaf(w, v.z, acc.z);
            acc.w = fmaf(w, v.w, acc.w);
        }
        out4[e * NH4 + h] = acc;
    }
}

extern "C" void kernel_launch(void* const* d_in, const int* in_sizes, int n_in,
                              void* d_out, int out_size)
{
    const float* rep   = (const float*)d_in[0];  // bond_representations [1,B,E,H]
    const int*   pairs = (const int*)  d_in[1];  // bond_pairs          [B,E,2]
    const int*   nbrs  = (const int*)  d_in[2];  // bond_neighbors      [B,E,K]
    const float* xyz   = (const float*)d_in[3];  // xyz                 [B,A,3]
    float*       out   = (float*)d_out;          // [1,B,E,H]

    dim3 grid(NB, HSPLIT);
    directed_edge_message_kernel<<<grid, 256>>>(rep, pairs, nbrs, xyz, out);
}

// round 3
// speedup vs baseline: 1.6804x; 1.1047x over previous
#include <cuda_runtime.h>
#include <cuda_bf16.h>
#include <math.h>

// Problem constants (fixed by the reference setup_inputs)
#define NB 256   // batches
#define NA 64    // atoms
#define NE 128   // edges per batch
#define NK 6     // neighbors per edge
#define NH 256   // hidden
#define NH4 (NH / 4)          // 64 float4 per edge row
#define HSPLIT 8              // CTAs per batch along H
#define NH4S (NH4 / HSPLIT)   // 8 float4 per edge per CTA
#define TILE (NE * NH4S)      // 1024 float4 staged per CTA (16 KB)

__global__ __launch_bounds__(256)
void directed_edge_message_kernel(const float* __restrict__ rep,     // [1,B,E,H]
                                  const int*   __restrict__ pairs,   // [B,E,2]
                                  const int*   __restrict__ nbrs,    // [B,E,K]
                                  const float* __restrict__ xyz,     // [B,A,3]
                                  float*       __restrict__ out)     // [1,B,E,H]
{
    const int b   = blockIdx.x;
    const int hs  = blockIdx.y;            // 0..HSPLIT-1
    const int tid = threadIdx.x;

    __shared__ float  dist_s[NE];
    __shared__ int    nb_s[NE * NK];
    __shared__ float4 ws4[TILE];           // dist-weighted rep slice [E][NH4S]

    // ---- Phase 1: per-edge inverse-squared-distance weight -----------------
    if (tid < NE) {
        const int base = (b * NE + tid) * 2;
        const int p0 = pairs[base + 0];
        const int p1 = pairs[base + 1];
        const float* x0 = xyz + ((size_t)b * NA + p0) * 3;
        const float* x1 = xyz + ((size_t)b * NA + p1) * 3;
        const float dx = x0[0] - x1[0];
        const float dy = x0[1] - x1[1];
        const float dz = x0[2] - x1[2];
        const float d2 = dx * dx + dy * dy + dz * dz;
        float inv = 1.0f / d2;
        // match jnp.where(isinf(inv), 0, inv)
        dist_s[tid] = isinf(inv) ? 0.0f : inv;
    }

    // Stage neighbor indices for this batch (E*K = 768 ints)
    #pragma unroll
    for (int i = tid; i < NE * NK; i += 256) {
        nb_s[i] = nbrs[(size_t)b * NE * NK + i];
    }
    __syncthreads();

    // ---- Phase 2: stage dist-weighted rep slice into SMEM ------------------
    const float4* __restrict__ rep4 = reinterpret_cast<const float4*>(rep + (size_t)b * NE * NH);
    float4*       __restrict__ out4 = reinterpret_cast<float4*>(out + (size_t)b * NE * NH);
    const int hbase = hs * NH4S;

    #pragma unroll
    for (int i = tid; i < TILE; i += 256) {
        const int e  = i >> 3;            // / NH4S
        const int hl = i & (NH4S - 1);
        const float  w = dist_s[e];
        const float4 v = rep4[e * NH4 + hbase + hl];
        ws4[i] = make_float4(w * v.x, w * v.y, w * v.z, w * v.w);
    }
    __syncthreads();

    // ---- Phase 3: gather from SMEM + sum -----------------------------------
    #pragma unroll
    for (int i = tid; i < TILE; i += 256) {
        const int e  = i >> 3;
        const int hl = i & (NH4S - 1);

        float4 acc = make_float4(0.f, 0.f, 0.f, 0.f);
        #pragma unroll
        for (int k = 0; k < NK; k++) {
            const int    nb = nb_s[e * NK + k];
            const float4 v  = ws4[nb * NH4S + hl];
            acc.x += v.x;
            acc.y += v.y;
            acc.z += v.z;
            acc.w += v.w;
        }
        out4[e * NH4 + hbase + hl] = acc;
    }
}

extern "C" void kernel_launch(void* const* d_in, const int* in_sizes, int n_in,
                              void* d_out, int out_size)
{
    const float* rep   = (const float*)d_in[0];  // bond_representations [1,B,E,H]
    const int*   pairs = (const int*)  d_in[1];  // bond_pairs          [B,E,2]
    const int*   nbrs  = (const int*)  d_in[2];  // bond_neighbors      [B,E,K]
    const float* xyz   = (const float*)d_in[3];  // xyz                 [B,A,3]
    float*       out   = (float*)d_out;          // [1,B,E,H]

    dim3 grid(NB, HSPLIT);
    directed_edge_message_kernel<<<grid, 256>>>(rep, pairs, nbrs, xyz, out);
}